// round 4
// baseline (speedup 1.0000x reference)
#include <cuda_runtime.h>
#include <math.h>

#define NN 1024
#define NT 256
#define BB 32

typedef unsigned long long u64;

// ---------------- device scratch ----------------
__device__ float2   g_pa[BB * NN];
__device__ float2   g_pam[BB * NN];
__device__ float2   g_tw[512];            // W_1024^k
__device__ double   g_accS[BB], g_accST[BB], g_accT[BB], g_accT2[BB];
__device__ unsigned g_accMax[BB];

__device__ __forceinline__ float2 cmulf(float2 a, float2 b) {
    return make_float2(a.x * b.x - a.y * b.y, a.x * b.y + a.y * b.x);
}

// ---------------- packed f32x2 helpers ----------------
__device__ __forceinline__ u64 pk2(float lo, float hi) {
    u64 r; asm("mov.b64 %0,{%1,%2};" : "=l"(r) : "f"(lo), "f"(hi)); return r;
}
__device__ __forceinline__ void upk2(u64 v, float& lo, float& hi) {
    asm("mov.b64 {%0,%1},%2;" : "=f"(lo), "=f"(hi) : "l"(v));
}
__device__ __forceinline__ u64 padd(u64 a, u64 b) {
    u64 r; asm("add.rn.f32x2 %0,%1,%2;" : "=l"(r) : "l"(a), "l"(b)); return r;
}
__device__ __forceinline__ u64 pmul(u64 a, u64 b) {
    u64 r; asm("mul.rn.f32x2 %0,%1,%2;" : "=l"(r) : "l"(a), "l"(b)); return r;
}
__device__ __forceinline__ u64 pfma(u64 a, u64 b, u64 c) {
    u64 r; asm("fma.rn.f32x2 %0,%1,%2,%3;" : "=l"(r) : "l"(a), "l"(b), "l"(c)); return r;
}
__device__ __forceinline__ u64 psub(u64 a, u64 b) {
    const u64 n1 = 0xBF800000BF800000ULL;  // (-1.0f, -1.0f)
    u64 r; asm("fma.rn.f32x2 %0,%1,%2,%3;" : "=l"(r) : "l"(b), "l"(n1), "l"(a)); return r;
}

struct PTw { u64 re, im, imn; };
__device__ __forceinline__ PTw mkptw(float2 w) {
    PTw t; t.re = pk2(w.x, w.x); t.im = pk2(w.y, w.y); t.imn = pk2(-w.y, -w.y); return t;
}
// in-place (re,im) *= tw
__device__ __forceinline__ void pcmul(u64& re, u64& im, const PTw& tw) {
    u64 nim = pfma(im, tw.re, pmul(re, tw.im));
    u64 nre = pfma(im, tw.imn, pmul(re, tw.re));
    re = nre; im = nim;
}

// radix-4 DIF butterfly on packed pairs, indices i0..i3 into Rr/Ri
#define PBFLY4(i0, i1, i2, i3, T1, T2, T3) do {                               \
    u64 t0r = padd(Rr[i0], Rr[i2]), t0i = padd(Ri[i0], Ri[i2]);               \
    u64 t1r = psub(Rr[i0], Rr[i2]), t1i = psub(Ri[i0], Ri[i2]);               \
    u64 t2r = padd(Rr[i1], Rr[i3]), t2i = padd(Ri[i1], Ri[i3]);               \
    u64 t3r = psub(Rr[i1], Rr[i3]), t3i = psub(Ri[i1], Ri[i3]);               \
    Rr[i0] = padd(t0r, t2r); Ri[i0] = padd(t0i, t2i);                         \
    { u64 br = padd(t1r, t3i), bi = psub(t1i, t3r); pcmul(br, bi, T1);        \
      Rr[i1] = br; Ri[i1] = bi; }                                             \
    { u64 cr = psub(t0r, t2r), ci = psub(t0i, t2i); pcmul(cr, ci, T2);        \
      Rr[i2] = cr; Ri[i2] = ci; }                                             \
    { u64 dr = psub(t1r, t3i), di = padd(t1i, t3r); pcmul(dr, di, T3);        \
      Rr[i3] = dr; Ri[i3] = di; }                                             \
} while (0)

// group barrier: 64 threads
__device__ __forceinline__ void gbar(int id) {
    asm volatile("bar.sync %0, %1;" :: "r"(id), "r"(64) : "memory");
}

// ---------------- radix-2 smem FFT (hilbert only) ----------------
template <bool INV>
__device__ __forceinline__ void fft1024(float2* sm, const float2* tw, int tid) {
#pragma unroll
    for (int e = 0; e < 4; e++) {
        int i = tid + e * NT;
        int j = __brev(i) >> 22;
        if (i < j) { float2 t = sm[i]; sm[i] = sm[j]; sm[j] = t; }
    }
    __syncthreads();
#pragma unroll
    for (int s = 1; s <= 10; s++) {
        int half = 1 << (s - 1);
#pragma unroll
        for (int e = 0; e < 2; e++) {
            int m   = tid + e * NT;
            int pos = m & (half - 1);
            int i0  = ((m >> (s - 1)) << s) + pos;
            int i1  = i0 + half;
            float2 w = tw[pos << (10 - s)];
            float wy = INV ? -w.y : w.y;
            float2 q = sm[i1];
            float2 v = make_float2(q.x * w.x - q.y * wy, q.x * wy + q.y * w.x);
            float2 u = sm[i0];
            sm[i0] = make_float2(u.x + v.x, u.y + v.y);
            sm[i1] = make_float2(u.x - v.x, u.y - v.y);
        }
        __syncthreads();
    }
    if (INV) {
        const float sc = 1.0f / (float)NN;
#pragma unroll
        for (int e = 0; e < 4; e++) { int i = tid + e * NT; sm[i].x *= sc; sm[i].y *= sc; }
        __syncthreads();
    }
}

// ---------------- kernel 1: init ----------------
__global__ void init_kernel(float* out) {
    int t = threadIdx.x;
    if (t == 0) out[0] = 0.0f;
    if (t < BB) {
        g_accS[t] = 0.0; g_accST[t] = 0.0; g_accT[t] = 0.0; g_accT2[t] = 0.0;
        g_accMax[t] = 0u;
    }
    if (t < 512) {
        double ang = -2.0 * 3.14159265358979323846 * (double)t / (double)NN;
        g_tw[t] = make_float2((float)cos(ang), (float)sin(ang));
    }
}

// ---------------- kernel 2: hilbert + modulation ----------------
__global__ void hilbert_kernel(const float* __restrict__ pred) {
    __shared__ float2 sm[NN];
    __shared__ float2 tw[NN / 2];
    int b = blockIdx.x, tid = threadIdx.x;
#pragma unroll
    for (int e = 0; e < 2; e++) tw[tid + e * NT] = g_tw[tid + e * NT];
#pragma unroll
    for (int e = 0; e < 4; e++) {
        int i = tid + e * NT;
        sm[i] = make_float2(pred[b * NN + i], 0.0f);
    }
    __syncthreads();
    fft1024<false>(sm, tw, tid);
#pragma unroll
    for (int e = 0; e < 4; e++) {
        int i = tid + e * NT;
        float h = (i < NN / 2) ? 0.0f : ((i == NN / 2) ? 1.0f : 2.0f);
        sm[i].x *= h; sm[i].y *= h;
    }
    __syncthreads();
    fft1024<true>(sm, tw, tid);
#pragma unroll
    for (int e = 0; e < 4; e++) {
        int i = tid + e * NT;
        float2 a = sm[i];
        g_pa[b * NN + i] = a;
        float ang = (float)(2.0 * 1175000000000000.0 * 1.5e-15 * (double)(i - 512));
        float cs = cosf(ang), sn = sinf(ang);
        g_pam[b * NN + i] = cmulf(a, make_float2(cs, -sn));
    }
}

// ---------------- kernel 3: SHG, row-paired packed radix-4 FFT ----------------
#define SWZ(t)  ((t) ^ (((t) >> 4) & 15))
#define TSWZ(k) ((k) ^ (((k) >> 4) & 15))

__global__ __launch_bounds__(256, 2) void shg_kernel(const float* __restrict__ tref) {
    extern __shared__ char sraw[];
    float2* paS  = (float2*)sraw;            // 1024
    float2* pamS = paS + NN;                 // 1024
    float2* twS  = pamS + NN;                // 256
    u64* workR   = (u64*)(twS + 256);        // 4*1024
    u64* workI   = workR + 4 * NN;           // 4*1024

    int tid = threadIdx.x;
    int b = blockIdx.y;
    int g = tid >> 6, lt = tid & 63;
    u64* wr = workR + g * NN;
    u64* wi = workI + g * NN;
    u64* trsm = wr;                          // overlay after exch2 reads

    for (int i = tid; i < NN; i += NT) { paS[i] = g_pa[b * NN + i]; pamS[i] = g_pam[b * NN + i]; }
    if (tid < 256) twS[tid] = g_tw[tid];
    __syncthreads();

    const u64 DT2pk = pk2(2.25e-30f, 2.25e-30f);
    const float* base = tref + (size_t)b * NN * NN;
    int mcoef = lt >> 2, ccoef = lt & 3;
    int kbase = 64 * (lt & 3) + 16 * ((lt >> 2) & 3) + 4 * (lt >> 4);

    float lmax = 0.0f;
    double dS = 0.0, dST = 0.0, dT = 0.0, dT2a = 0.0;

    u64 Rr[16], Ri[16];

    for (int rr = 0; rr < 2; rr++) {
        int d0 = blockIdx.x * 16 + g * 4 + rr * 2;   // rows d0, d0+1
        int delay0 = d0 - 512;

        // input build: c[t] = pam[t] * pa[(t-delay) & 1023], packed (row0,row1)
#pragma unroll
        for (int e = 0; e < 16; e++) {
            int t = lt + 64 * e;
            float2 pm = pamS[t];
            int t20 = (t - delay0) & (NN - 1);
            float2 p0 = paS[t20];
            float2 p1 = paS[(t20 - 1) & (NN - 1)];
            u64 are = pk2(pm.x, pm.x), aim = pk2(pm.y, pm.y);
            u64 bre = pk2(p0.x, p1.x), bim = pk2(p0.y, p1.y);
            Rr[e] = psub(pmul(are, bre), pmul(aim, bim));
            Ri[e] = pfma(aim, bre, pmul(are, bim));
        }
        // stage 0 (L=1024)
#pragma unroll
        for (int c2 = 0; c2 < 4; c2++) {
            float2 w1 = twS[lt + 64 * c2];
            float2 w2 = cmulf(w1, w1), w3 = cmulf(w1, w2);
            PTw T1 = mkptw(w1), T2 = mkptw(w2), T3 = mkptw(w3);
            PBFLY4(c2, c2 + 4, c2 + 8, c2 + 12, T1, T2, T3);
        }
        // stage 1 (L=256)
        {
            float2 w1 = twS[4 * lt];
            float2 w2 = cmulf(w1, w1), w3 = cmulf(w1, w2);
            PTw T1 = mkptw(w1), T2 = mkptw(w2), T3 = mkptw(w3);
#pragma unroll
            for (int B = 0; B < 4; B++)
                PBFLY4(4 * B, 4 * B + 1, 4 * B + 2, 4 * B + 3, T1, T2, T3);
        }
        // exchange 1: layout A -> layout B
#pragma unroll
        for (int e = 0; e < 16; e++) { int s = SWZ(lt + 64 * e); wr[s] = Rr[e]; wi[s] = Ri[e]; }
        gbar(g + 1);
#pragma unroll
        for (int j = 0; j < 16; j++) {
            int s = SWZ(64 * mcoef + ccoef + 4 * j);
            Rr[j] = wr[s]; Ri[j] = wi[s];
        }
        // issue tref loads for both rows now (consumed after exch2)
        const float4* r0p = (const float4*)(base + (size_t)d0 * NN);
        const float4* r1p = (const float4*)(base + (size_t)(d0 + 1) * NN);
        float4 tv0[4], tv1[4];
#pragma unroll
        for (int j = 0; j < 4; j++) { tv0[j] = r0p[lt + 64 * j]; tv1[j] = r1p[lt + 64 * j]; }

        // stage 2 (L=64)
#pragma unroll
        for (int j0 = 0; j0 < 4; j0++) {
            float2 w1 = twS[16 * (ccoef + 4 * j0)];
            float2 w2 = cmulf(w1, w1), w3 = cmulf(w1, w2);
            PTw T1 = mkptw(w1), T2 = mkptw(w2), T3 = mkptw(w3);
            PBFLY4(j0, j0 + 4, j0 + 8, j0 + 12, T1, T2, T3);
        }
        // stage 3 (L=16)
        {
            float2 w1 = twS[64 * ccoef];
            float2 w2 = cmulf(w1, w1), w3 = cmulf(w1, w2);
            PTw T1 = mkptw(w1), T2 = mkptw(w2), T3 = mkptw(w3);
#pragma unroll
            for (int h = 0; h < 4; h++)
                PBFLY4(4 * h, 4 * h + 1, 4 * h + 2, 4 * h + 3, T1, T2, T3);
        }
        gbar(g + 1);   // exch1 reads complete before overwrite
        // exchange 2: layout B -> layout C
#pragma unroll
        for (int j = 0; j < 16; j++) {
            int s = SWZ(64 * mcoef + ccoef + 4 * j);
            wr[s] = Rr[j]; wi[s] = Ri[j];
        }
        gbar(g + 1);
#pragma unroll
        for (int v = 0; v < 4; v++)
#pragma unroll
            for (int u = 0; u < 4; u++) {
                int s = SWZ(4 * lt + 256 * v + u);
                Rr[4 * v + u] = wr[s]; Ri[4 * v + u] = wi[s];
            }
        gbar(g + 1);   // exch2 reads done; wr free -> stage trs there

        // stage tref pair (packed) + rT/rT2 reductions
        u64 rT_pk = pk2(0.f, 0.f), rT2_pk = rT_pk;
#pragma unroll
        for (int j = 0; j < 4; j++) {
            float v0[4] = { tv0[j].x, tv0[j].y, tv0[j].z, tv0[j].w };
            float v1[4] = { tv1[j].x, tv1[j].y, tv1[j].z, tv1[j].w };
#pragma unroll
            for (int q = 0; q < 4; q++) {
                int col = 4 * (lt + 64 * j) + q;
                u64 tp = pk2(v0[q], v1[q]);
                trsm[TSWZ(col)] = tp;
                rT_pk  = padd(rT_pk, tp);
                rT2_pk = pfma(tp, tp, rT2_pk);
            }
        }
        gbar(g + 1);

        // stage 4 (L=4) + magnitude + fused reductions
        u64 rS_pk = pk2(0.f, 0.f), rST_pk = rS_pk;
#pragma unroll
        for (int v = 0; v < 4; v++) {
            int i0 = 4 * v;
            u64 t0r = padd(Rr[i0], Rr[i0 + 2]), t0i = padd(Ri[i0], Ri[i0 + 2]);
            u64 t1r = psub(Rr[i0], Rr[i0 + 2]), t1i = psub(Ri[i0], Ri[i0 + 2]);
            u64 t2r = padd(Rr[i0 + 1], Rr[i0 + 3]), t2i = padd(Ri[i0 + 1], Ri[i0 + 3]);
            u64 t3r = psub(Rr[i0 + 1], Rr[i0 + 3]), t3i = psub(Ri[i0 + 1], Ri[i0 + 3]);
            u64 yr[4], yi[4];
            yr[0] = padd(t0r, t2r); yi[0] = padd(t0i, t2i);
            yr[1] = padd(t1r, t3i); yi[1] = psub(t1i, t3r);
            yr[2] = psub(t0r, t2r); yi[2] = psub(t0i, t2i);
            yr[3] = psub(t1r, t3i); yi[3] = padd(t1i, t3r);
#pragma unroll
            for (int u = 0; u < 4; u++) {
                u64 sp = pfma(yr[u], yr[u], pmul(yi[u], yi[u]));
                sp = pmul(sp, DT2pk);
                int k2 = (256 * u + kbase + v) ^ 512;
                u64 tq = trsm[TSWZ(k2)];
                rS_pk  = padd(rS_pk, sp);
                rST_pk = pfma(sp, tq, rST_pk);
                float s0, s1; upk2(sp, s0, s1);
                lmax = fmaxf(lmax, fmaxf(s0, s1));
            }
        }
        gbar(g + 1);   // trs reads done before next iter's exch1 writes

        { float a0, a1;
          upk2(rS_pk, a0, a1);  dS   += (double)a0 + (double)a1;
          upk2(rST_pk, a0, a1); dST  += (double)a0 + (double)a1;
          upk2(rT_pk, a0, a1);  dT   += (double)a0 + (double)a1;
          upk2(rT2_pk, a0, a1); dT2a += (double)a0 + (double)a1; }
    }

    // block reduction
    double vS = dS, vST = dST, vT = dT, vT2 = dT2a; float vM = lmax;
#pragma unroll
    for (int o = 16; o > 0; o >>= 1) {
        vS  += __shfl_down_sync(0xffffffffu, vS,  o);
        vST += __shfl_down_sync(0xffffffffu, vST, o);
        vT  += __shfl_down_sync(0xffffffffu, vT,  o);
        vT2 += __shfl_down_sync(0xffffffffu, vT2, o);
        vM   = fmaxf(vM, __shfl_down_sync(0xffffffffu, vM, o));
    }
    __shared__ double sS[8], sST[8], sT[8], sT2[8];
    __shared__ float  sM[8];
    int w = tid >> 5, lane = tid & 31;
    if (lane == 0) { sS[w] = vS; sST[w] = vST; sT[w] = vT; sT2[w] = vT2; sM[w] = vM; }
    __syncthreads();
    if (tid == 0) {
        double aS = 0, aST = 0, aT = 0, aT2 = 0; float aM = 0.0f;
#pragma unroll
        for (int i = 0; i < 8; i++) {
            aS += sS[i]; aST += sST[i]; aT += sT[i]; aT2 += sT2[i];
            aM = fmaxf(aM, sM[i]);
        }
        atomicAdd(&g_accS[b],  aS);
        atomicAdd(&g_accST[b], aST);
        atomicAdd(&g_accT[b],  aT);
        atomicAdd(&g_accT2[b], aT2);
        atomicMax(&g_accMax[b], __float_as_uint(aM));
    }
}

// ---------------- kernel 4: MSE + frog + final mean ----------------
__global__ void loss_kernel(const float* __restrict__ label, float* out) {
    int b = blockIdx.x, tid = threadIdx.x;
    const float* lr = label + (size_t)b * 2 * NN;
    const float* li = lr + NN;

    __shared__ int s_frR, s_laR, s_frI, s_laI;
    if (tid == 0) { s_frR = NN; s_laR = -1; s_frI = NN; s_laI = -1; }
    __syncthreads();
    int frR = NN, laR = -1, frI = NN, laI = -1;
    for (int t = tid; t < NN; t += NT) {
        if (fabsf(lr[t]) > 0.01f) { frR = min(frR, t); laR = max(laR, t); }
        if (fabsf(li[t]) > 0.01f) { frI = min(frI, t); laI = max(laI, t); }
    }
    atomicMin(&s_frR, frR); atomicMax(&s_laR, laR);
    atomicMin(&s_frI, frI); atomicMax(&s_laI, laI);
    __syncthreads();
    int fr_r = (s_frR == NN) ? 0 : s_frR;
    int la_r = (s_laR < 0) ? (NN - 1) : s_laR;
    int fr_i = (s_frI == NN) ? 0 : s_frI;
    int la_i = (s_laI < 0) ? (NN - 1) : s_laI;
    int first = min(fr_r, fr_i);
    int last  = max(la_r, la_i);

    float sR = 0, sI = 0, sInt = 0, sPh = 0;
    for (int t = tid; t < NN; t += NT) {
        float2 p = g_pa[b * NN + t];
        float LR = lr[t], LI = li[t];
        bool inr = (t >= first) && (t < last);
        float pm = inr ? 10.0f : 1.0f;
        float dr = p.x - LR, di = p.y - LI;
        float pint = p.x * p.x + p.y * p.y;
        float lint = LR * LR + LI * LI;
        float dint = pint - lint;
        sR   += dr * dr * pm;
        sI   += di * di * pm;
        sInt += dint * dint * pm;
        if (inr) {
            float dp = atan2f(p.y, p.x) - atan2f(LI, LR);
            sPh += dp * dp;
        }
    }
#pragma unroll
    for (int o = 16; o > 0; o >>= 1) {
        sR   += __shfl_down_sync(0xffffffffu, sR, o);
        sI   += __shfl_down_sync(0xffffffffu, sI, o);
        sInt += __shfl_down_sync(0xffffffffu, sInt, o);
        sPh  += __shfl_down_sync(0xffffffffu, sPh, o);
    }
    __shared__ float rA[8], rBv[8], rC[8], rD[8];
    int w = tid >> 5, lane = tid & 31;
    if (lane == 0) { rA[w] = sR; rBv[w] = sI; rC[w] = sInt; rD[w] = sPh; }
    __syncthreads();
    if (tid == 0) {
        float aR = 0, aI = 0, aInt = 0, aPh = 0;
#pragma unroll
        for (int i = 0; i < 8; i++) { aR += rA[i]; aI += rBv[i]; aInt += rC[i]; aPh += rD[i]; }
        float mse = (aR + aI + aInt + aPh) * (1.0f / NN) * 0.25f;

        double M    = (double)__uint_as_float(g_accMax[b]);
        double sum1 = g_accST[b] / M;
        double mu   = sum1 / g_accT2[b];
        double diff = g_accS[b] / M - mu * g_accT[b];
        double r2   = diff * diff;
        float frog = (r2 == 0.0) ? 0.0f : (float)(sqrt(r2) / (double)NN);

        atomicAdd(out, (mse + frog) * (1.0f / BB));
    }
}

// ---------------- launch ----------------
extern "C" void kernel_launch(void* const* d_in, const int* in_sizes, int n_in,
                              void* d_out, int out_size) {
    const float* pred  = (const float*)d_in[0];
    const float* label = (const float*)d_in[1];
    const float* shg   = (const float*)d_in[2];
    float* out = (float*)d_out;

    const int SHG_SMEM = (2 * NN + 256) * sizeof(float2) + 2 * 4 * NN * sizeof(u64);
    static int attr_done = 0;
    if (!attr_done) {
        cudaFuncSetAttribute(shg_kernel, cudaFuncAttributeMaxDynamicSharedMemorySize, SHG_SMEM);
        attr_done = 1;
    }

    init_kernel<<<1, 512>>>(out);
    hilbert_kernel<<<BB, NT>>>(pred);
    shg_kernel<<<dim3(64, BB), NT, SHG_SMEM>>>(shg);
    loss_kernel<<<BB, NT>>>(label, out);
}